// round 3
// baseline (speedup 1.0000x reference)
#include <cuda_runtime.h>
#include <cuda_bf16.h>

// Weighted BCE mean reduction, single fused kernel.
// loss_i = y_i==1 ? -log(x_i)*w1 : -log(1-x_i)*w0 ; out = mean(loss)
// N = 33554432. HBM-bound: 256 MB mandatory read.
// R3: __ldcs streaming loads + unroll-4 (8 front-batched LDG.128 per iter).

#define RBLOCKS 1184          // 148 SMs * 8
#define RTHREADS 256

__device__ float g_partials[RBLOCKS];
__device__ unsigned int g_count;   // zero-init; reset by last block each replay

__global__ __launch_bounds__(RTHREADS)
void wbce_kernel(const float4* __restrict__ x4,
                 const int4* __restrict__ y4,
                 const float* __restrict__ w,
                 int n4, float inv_n,
                 float* __restrict__ out)
{
    const float w0 = __ldg(&w[0]);
    const float w1 = __ldg(&w[1]);

    float acc = 0.0f;
    const int stride = gridDim.x * blockDim.x;
    int i = blockIdx.x * blockDim.x + threadIdx.x;

    // unroll x4: 8 wide streaming loads issued back-to-back before any math
    for (; i + 3 * stride < n4; i += 4 * stride) {
        float4 xa[4];
        int4   ya[4];
        #pragma unroll
        for (int j = 0; j < 4; j++) xa[j] = __ldcs(&x4[i + j * stride]);
        #pragma unroll
        for (int j = 0; j < 4; j++) ya[j] = __ldcs(&y4[i + j * stride]);

        #pragma unroll
        for (int j = 0; j < 4; j++) {
            float t0 = (ya[j].x == 1) ? xa[j].x : (1.0f - xa[j].x);
            float t1 = (ya[j].y == 1) ? xa[j].y : (1.0f - xa[j].y);
            float t2 = (ya[j].z == 1) ? xa[j].z : (1.0f - xa[j].z);
            float t3 = (ya[j].w == 1) ? xa[j].w : (1.0f - xa[j].w);
            float u0 = (ya[j].x == 1) ? w1 : w0;
            float u1 = (ya[j].y == 1) ? w1 : w0;
            float u2 = (ya[j].z == 1) ? w1 : w0;
            float u3 = (ya[j].w == 1) ? w1 : w0;
            acc = fmaf(-__logf(t0), u0, acc);
            acc = fmaf(-__logf(t1), u1, acc);
            acc = fmaf(-__logf(t2), u2, acc);
            acc = fmaf(-__logf(t3), u3, acc);
        }
    }
    // tail (up to 3 strided float4s per thread)
    for (; i < n4; i += stride) {
        float4 xv = __ldcs(&x4[i]);
        int4   yv = __ldcs(&y4[i]);
        float t0 = (yv.x == 1) ? xv.x : (1.0f - xv.x);
        float t1 = (yv.y == 1) ? xv.y : (1.0f - xv.y);
        float t2 = (yv.z == 1) ? xv.z : (1.0f - xv.z);
        float t3 = (yv.w == 1) ? xv.w : (1.0f - xv.w);
        float u0 = (yv.x == 1) ? w1 : w0;
        float u1 = (yv.y == 1) ? w1 : w0;
        float u2 = (yv.z == 1) ? w1 : w0;
        float u3 = (yv.w == 1) ? w1 : w0;
        acc = fmaf(-__logf(t0), u0, acc);
        acc = fmaf(-__logf(t1), u1, acc);
        acc = fmaf(-__logf(t2), u2, acc);
        acc = fmaf(-__logf(t3), u3, acc);
    }

    // intra-block reduce
    #pragma unroll
    for (int off = 16; off > 0; off >>= 1)
        acc += __shfl_xor_sync(0xFFFFFFFFu, acc, off);

    __shared__ float warp_sums[RTHREADS / 32];
    __shared__ bool s_is_last;
    int lane = threadIdx.x & 31;
    int wid  = threadIdx.x >> 5;
    if (lane == 0) warp_sums[wid] = acc;
    __syncthreads();

    if (wid == 0) {
        float v = (lane < RTHREADS / 32) ? warp_sums[lane] : 0.0f;
        #pragma unroll
        for (int off = 16; off > 0; off >>= 1)
            v += __shfl_xor_sync(0xFFFFFFFFu, v, off);
        if (lane == 0) {
            g_partials[blockIdx.x] = v;
            __threadfence();
            unsigned int t = atomicAdd(&g_count, 1u);
            s_is_last = (t == gridDim.x - 1);
        }
    }
    __syncthreads();

    // last block folds all partials -> out
    if (s_is_last) {
        volatile float* parts = g_partials;
        float a = 0.0f;
        for (int j = threadIdx.x; j < RBLOCKS; j += RTHREADS)
            a += parts[j];

        #pragma unroll
        for (int off = 16; off > 0; off >>= 1)
            a += __shfl_xor_sync(0xFFFFFFFFu, a, off);

        if (lane == 0) warp_sums[wid] = a;
        __syncthreads();

        if (wid == 0) {
            float v = (lane < RTHREADS / 32) ? warp_sums[lane] : 0.0f;
            #pragma unroll
            for (int off = 16; off > 0; off >>= 1)
                v += __shfl_xor_sync(0xFFFFFFFFu, v, off);
            if (lane == 0) {
                out[0] = v * inv_n;
                g_count = 0;          // reset for next graph replay
            }
        }
    }
}

extern "C" void kernel_launch(void* const* d_in, const int* in_sizes, int n_in,
                              void* d_out, int out_size)
{
    const float* x = (const float*)d_in[0];
    const int*   y = (const int*)d_in[1];
    const float* w = (const float*)d_in[2];
    float* out = (float*)d_out;

    int n  = in_sizes[0];
    int n4 = n / 4;

    wbce_kernel<<<RBLOCKS, RTHREADS>>>(
        (const float4*)x, (const int4*)y, w, n4, 1.0f / (float)n, out);
}